// round 7
// baseline (speedup 1.0000x reference)
#include <cuda_runtime.h>
#include <cstdint>

// Problem constants: B=32, L=256, C=16, D=128, char vocab = 128.
// out: float32 [2, 32, 128, 256]; out[0]=word conv, out[1]=char feats (transposed).

__device__ float g_Wt_word[3 * 128 * 128];  // [k][din][dout]
__device__ float g_P      [128 * 3 * 128];  // [c][k][dout], bias folded into k=1

// ---------------------------------------------------------------------------
// K1 "setup": blocks 0-191 transpose word weights [dout][din][k]->[k][din][dout];
// blocks 192-255 compute P[c][k][dout] (2 c's per block) straight from the
// ORIGINAL chr-weight layout via a 387-pitch smem stage (no transpose needed).
// ---------------------------------------------------------------------------
#define WPITCH 387   // 384 + 3; 387 % 32 = 3, gcd(3,32)=1 -> conflict-free reads

__global__ void k_setup(const float* __restrict__ ww, const float* __restrict__ wc,
                        const float* __restrict__ ctab, const float* __restrict__ wcb) {
    int tid = threadIdx.x;  // 256
    if (blockIdx.x < 192) {
        int o = blockIdx.x * 256 + tid;                  // 192*256 = 49152
        int k = o >> 14, r = o & 16383, din = r >> 7, dout = r & 127;
        g_Wt_word[o] = ww[dout * 384 + din * 3 + k];
        return;
    }
    extern __shared__ float s[];
    float* Wst  = s;                   // 128 * 387 floats
    float* erow = s + 128 * WPITCH;    // 2 * 128 floats
    int blk = blockIdx.x - 192;        // 0..63

    // stage chr weights: Wst[d*387 + r] = wc[d*384 + r]  (coalesced reads)
    {
        int o = tid;
        int d = 0, r = tid;            // tid < 384 always (256)
        for (; o < 49152; o += 256) {
            Wst[d * WPITCH + r] = wc[o];
            r += 256;
            if (r >= 384) { r -= 384; d++; }
        }
    }
    int c0 = blk * 2;
    int sub = tid >> 7, d = tid & 127;
    erow[sub * 128 + d] = ctab[(c0 + sub) * 128 + d];
    __syncthreads();

    const float* er = erow + sub * 128;
    const float* wr = Wst + d * WPITCH;
    float a0 = 0.f, a1 = 0.f, a2 = 0.f;
#pragma unroll 4
    for (int din = 0; din < 128; din++) {
        float e = er[din];
        a0 = fmaf(e, wr[din * 3 + 0], a0);
        a1 = fmaf(e, wr[din * 3 + 1], a1);
        a2 = fmaf(e, wr[din * 3 + 2], a2);
    }
    int c = c0 + sub;
    g_P[(c * 3 + 0) * 128 + d] = a0;
    g_P[(c * 3 + 1) * 128 + d] = a1 + wcb[d];   // bias folded into center tap
    g_P[(c * 3 + 2) * 128 + d] = a2;
}
#define SMEM_SETUP ((128 * WPITCH + 256) * 4)   // 199168 B

// ---------------------------------------------------------------------------
// K2 "main": fused word-GEMM + char-path kernel.
//   bid 0..255   : word blocks, 32-token x 128-dout tile (b = bid>>3, chunk = bid&7)
//   bid 256..383 : char blocks, 64-token chunk with P in smem
// ---------------------------------------------------------------------------
#define CP16(dst_s, src_g) \
    asm volatile("cp.async.cg.shared.global [%0], [%1], 16;\n" :: "r"(dst_s), "l"(src_g))

#define SMEM_MAIN 229888   // char variant: 49152 (P) + 8320 (Fs) floats

__global__ void __launch_bounds__(256, 1)
k_main(const int* __restrict__ wv, const float* __restrict__ wtab,
       const float* __restrict__ wb, const int* __restrict__ wic,
       float* __restrict__ out0, float* __restrict__ out1) {
    extern __shared__ float sm[];
    int tid = threadIdx.x;  // 256
    int bid = blockIdx.x;

    if (bid < 256) {
        // ================= WORD PATH: 32-token tile =================
        float* Es = sm;                 // 34 * 128 floats (token halo)
        float* Ws = sm + 34 * 128;      // 2 * 16384 floats (double-buffered tap)
        int b  = bid >> 3;
        int t0 = (bid & 7) << 5;

        unsigned ws_base = (unsigned)__cvta_generic_to_shared(Ws);
        {   // prefetch tap 0 weights into buffer 0
            const float* g0 = g_Wt_word;
#pragma unroll
            for (int i = 0; i < 16; i++) {
                int o4 = tid + i * 256;
                CP16(ws_base + o4 * 16, g0 + o4 * 4);
            }
            asm volatile("cp.async.commit_group;\n");
        }
        // embedding gather: rows v=0..33 <-> global token t0+v-1 (zero padded)
        for (int item = tid; item < 34 * 32; item += 256) {
            int v = item >> 5, q = item & 31;
            int gt = t0 + v - 1;
            float4 val = make_float4(0.f, 0.f, 0.f, 0.f);
            if ((unsigned)gt < 256u) {
                int idx = __ldg(wv + (b << 8) + gt);
                val = __ldg((const float4*)wtab + idx * 32 + q);
            }
            ((float4*)Es)[(v << 5) + q] = val;
        }
        asm volatile("cp.async.wait_group 0;\n");
        __syncthreads();

        int warp = tid >> 5, col = tid & 31;
        int tb = warp << 2;            // 4 tokens per warp
        float acc[4][4];
#pragma unroll
        for (int i = 0; i < 4; i++)
            acc[i][0] = acc[i][1] = acc[i][2] = acc[i][3] = 0.f;

#pragma unroll
        for (int tap = 0; tap < 3; tap++) {
            if (tap < 2) {   // prefetch next tap into the other buffer
                const float* gn = g_Wt_word + (tap + 1) * 16384;
                unsigned dstb = ws_base + (((tap + 1) & 1) * 16384) * 4;
#pragma unroll
                for (int i = 0; i < 16; i++) {
                    int o4 = tid + i * 256;
                    CP16(dstb + o4 * 16, gn + o4 * 4);
                }
                asm volatile("cp.async.commit_group;\n");
            }
            const float* W  = Ws + (tap & 1) * 16384;
            const float* Er = Es + (tb + tap) * 128;
#pragma unroll 4
            for (int din = 0; din < 128; din++) {
                float4 w = ((const float4*)(W + din * 128))[col];
                float e0 = Er[din];
                float e1 = Er[128 + din];
                float e2 = Er[256 + din];
                float e3 = Er[384 + din];
                acc[0][0] = fmaf(e0, w.x, acc[0][0]);
                acc[0][1] = fmaf(e0, w.y, acc[0][1]);
                acc[0][2] = fmaf(e0, w.z, acc[0][2]);
                acc[0][3] = fmaf(e0, w.w, acc[0][3]);
                acc[1][0] = fmaf(e1, w.x, acc[1][0]);
                acc[1][1] = fmaf(e1, w.y, acc[1][1]);
                acc[1][2] = fmaf(e1, w.z, acc[1][2]);
                acc[1][3] = fmaf(e1, w.w, acc[1][3]);
                acc[2][0] = fmaf(e2, w.x, acc[2][0]);
                acc[2][1] = fmaf(e2, w.y, acc[2][1]);
                acc[2][2] = fmaf(e2, w.z, acc[2][2]);
                acc[2][3] = fmaf(e2, w.w, acc[2][3]);
                acc[3][0] = fmaf(e3, w.x, acc[3][0]);
                acc[3][1] = fmaf(e3, w.y, acc[3][1]);
                acc[3][2] = fmaf(e3, w.z, acc[3][2]);
                acc[3][3] = fmaf(e3, w.w, acc[3][3]);
            }
            if (tap < 2) {
                asm volatile("cp.async.wait_group 0;\n");
                __syncthreads();
            }
        }
        // epilogue: bias + float4 store of 4 consecutive tokens per dout
#pragma unroll
        for (int j = 0; j < 4; j++) {
            int dout = (col << 2) + j;
            float bias = __ldg(wb + dout);
            float4 v = make_float4(acc[0][j] + bias, acc[1][j] + bias,
                                   acc[2][j] + bias, acc[3][j] + bias);
            *(float4*)(out0 + (((b << 7) + dout) << 8) + t0 + tb) = v;
        }
        return;
    }

    // ================= CHAR PATH: 64-token chunk =================
    {
        float* Ps = sm;              // 49152 floats
        float* Fs = sm + 49152;      // 128 * 65 floats
        int cb = bid - 256;
        int b  = cb >> 2;
        int t0 = (cb & 3) << 6;

        {   // load P into smem (L2-resident: 192 KB)
            const float4* src = (const float4*)g_P;
            float4* dst = (float4*)Ps;
#pragma unroll
            for (int i = 0; i < 48; i++) dst[tid + i * 256] = src[tid + i * 256];
        }
        __syncthreads();

        int warp = tid >> 5, lane = tid & 31;
        int d4 = lane << 2;

#define PL(cc, kk) (*(const float4*)&Ps[((cc) * 3 + (kk)) * 128 + d4])

        for (int ii = 0; ii < 8; ii++) {
            int lw = warp * 8 + ii;
            const int4* ip = (const int4*)(wic + (((b << 8) + t0 + lw) << 4));
            int4 q0 = ip[0], q1 = ip[1], q2 = ip[2], q3 = ip[3];
            int c[16] = {q0.x, q0.y, q0.z, q0.w, q1.x, q1.y, q1.z, q1.w,
                         q2.x, q2.y, q2.z, q2.w, q3.x, q3.y, q3.z, q3.w};

            float4 a = PL(c[0], 1);
            float4 r = PL(c[1], 2);
            float4 m;
            m.x = a.x + r.x; m.y = a.y + r.y; m.z = a.z + r.z; m.w = a.w + r.w;
#pragma unroll
            for (int t = 1; t < 15; t++) {
                float4 ce = PL(c[t], 1);
                float4 le = PL(c[t - 1], 0);
                float4 re = PL(c[t + 1], 2);
                float vx = ce.x + le.x + re.x;
                float vy = ce.y + le.y + re.y;
                float vz = ce.z + le.z + re.z;
                float vw = ce.w + le.w + re.w;
                m.x = fmaxf(m.x, vx); m.y = fmaxf(m.y, vy);
                m.z = fmaxf(m.z, vz); m.w = fmaxf(m.w, vw);
            }
            {
                float4 ce = PL(c[15], 1);
                float4 le = PL(c[14], 0);
                m.x = fmaxf(m.x, ce.x + le.x); m.y = fmaxf(m.y, ce.y + le.y);
                m.z = fmaxf(m.z, ce.z + le.z); m.w = fmaxf(m.w, ce.w + le.w);
            }
            Fs[(d4 + 0) * 65 + lw] = m.x;
            Fs[(d4 + 1) * 65 + lw] = m.y;
            Fs[(d4 + 2) * 65 + lw] = m.z;
            Fs[(d4 + 3) * 65 + lw] = m.w;
        }
#undef PL
        __syncthreads();

        int dout = tid >> 1;
        int half = tid & 1;
        const float* fsrc = Fs + dout * 65 + (half << 5);
        float* gdst = out1 + (((b << 7) + dout) << 8) + t0 + (half << 5);
#pragma unroll
        for (int i = 0; i < 8; i++) {
            float4 v = make_float4(fsrc[i * 4 + 0], fsrc[i * 4 + 1],
                                   fsrc[i * 4 + 2], fsrc[i * 4 + 3]);
            ((float4*)gdst)[i] = v;
        }
    }
}

// ---------------------------------------------------------------------------
extern "C" void kernel_launch(void* const* d_in, const int* in_sizes, int n_in,
                              void* d_out, int out_size) {
    const int*   wv   = (const int*)d_in[0];    // word_vector  [32,256]
    const int*   wic  = (const int*)d_in[1];    // words_in_char [32,256,16]
    const float* wtab = (const float*)d_in[2];  // word_table [50000,128]
    const float* ctab = (const float*)d_in[3];  // chr_table [128,128]
    const float* wcw  = (const float*)d_in[4];  // conv_chr_w [128,128,3]
    const float* wcb  = (const float*)d_in[5];  // conv_chr_b [128]
    const float* www  = (const float*)d_in[6];  // conv_word_w [128,128,3]
    const float* wwb  = (const float*)d_in[7];  // conv_word_b [128]
    float* out  = (float*)d_out;
    float* out0 = out;                    // [32,128,256] word conv
    float* out1 = out + 32 * 128 * 256;   // [32,128,256] char feats

    cudaFuncSetAttribute(k_setup, cudaFuncAttributeMaxDynamicSharedMemorySize, SMEM_SETUP);
    cudaFuncSetAttribute(k_main,  cudaFuncAttributeMaxDynamicSharedMemorySize, SMEM_MAIN);

    k_setup<<<256, 256, SMEM_SETUP>>>(www, wcw, ctab, wcb);
    k_main<<<384, 256, SMEM_MAIN>>>(wv, wtab, wwb, wic, out0, out1);
}

// round 9
// speedup vs baseline: 1.0714x; 1.0714x over previous
#include <cuda_runtime.h>
#include <cstdint>

// Problem constants: B=32, L=256, C=16, D=128, char vocab = 128.
// out: float32 [2, 32, 128, 256]; out[0]=word conv, out[1]=char feats (transposed).

__device__ float g_Wt_word[3 * 128 * 128];  // [k][din][dout]
__device__ float g_P      [128 * 3 * 128];  // [c][k][dout], bias folded into k=1

// ---------------------------------------------------------------------------
// K1 "setup": blocks 0-191 transpose word weights [dout][din][k]->[k][din][dout];
// blocks 192-255 compute P[c][k][dout] (2 c's per block) straight from the
// ORIGINAL chr-weight layout via a 387-pitch smem stage (no transpose needed).
// ---------------------------------------------------------------------------
#define WPITCH 387   // 384 + 3; gcd-based pitch -> conflict-free strided reads

__global__ void k_setup(const float* __restrict__ ww, const float* __restrict__ wc,
                        const float* __restrict__ ctab, const float* __restrict__ wcb) {
    int tid = threadIdx.x;  // 256
    if (blockIdx.x < 192) {
        int o = blockIdx.x * 256 + tid;                  // 192*256 = 49152
        int k = o >> 14, r = o & 16383, din = r >> 7, dout = r & 127;
        g_Wt_word[o] = ww[dout * 384 + din * 3 + k];
        return;
    }
    extern __shared__ float s[];
    float* Wst  = s;                   // 128 * 387 floats
    float* erow = s + 128 * WPITCH;    // 2 * 128 floats
    int blk = blockIdx.x - 192;        // 0..63

    {   // stage chr weights: Wst[d*387 + r] = wc[d*384 + r]  (coalesced reads)
        int o = tid;
        int d = 0, r = tid;
        for (; o < 49152; o += 256) {
            Wst[d * WPITCH + r] = wc[o];
            r += 256;
            if (r >= 384) { r -= 384; d++; }
        }
    }
    int c0 = blk * 2;
    int sub = tid >> 7, d = tid & 127;
    erow[sub * 128 + d] = ctab[(c0 + sub) * 128 + d];
    __syncthreads();

    const float* er = erow + sub * 128;
    const float* wr = Wst + d * WPITCH;
    float a0 = 0.f, a1 = 0.f, a2 = 0.f;
#pragma unroll 4
    for (int din = 0; din < 128; din++) {
        float e = er[din];
        a0 = fmaf(e, wr[din * 3 + 0], a0);
        a1 = fmaf(e, wr[din * 3 + 1], a1);
        a2 = fmaf(e, wr[din * 3 + 2], a2);
    }
    int c = c0 + sub;
    g_P[(c * 3 + 0) * 128 + d] = a0;
    g_P[(c * 3 + 1) * 128 + d] = a1 + wcb[d];   // bias folded into center tap
    g_P[(c * 3 + 2) * 128 + d] = a2;
}
#define SMEM_SETUP ((128 * WPITCH + 256) * 4)   // 199168 B

// ---------------------------------------------------------------------------
// K2: char path (R2 version). Block = (b, 64-token chunk). P in smem (192 KB).
// Warp handles 8 words; lane owns a dout-quad -> conflict-free LDS.128.
// ---------------------------------------------------------------------------
__global__ void k_char(const int* __restrict__ wic, float* __restrict__ out1) {
    extern __shared__ float sm[];
    float* Ps = sm;              // 49152 floats
    float* Fs = sm + 49152;      // 128 * 65 floats
    int tid = threadIdx.x;       // 256 threads
    int b  = blockIdx.x >> 2;
    int t0 = (blockIdx.x & 3) << 6;

    {   // load P into smem (L2-resident: 192 KB)
        const float4* src = (const float4*)g_P;
        float4* dst = (float4*)Ps;
#pragma unroll
        for (int i = 0; i < 48; i++) dst[tid + i * 256] = src[tid + i * 256];
    }
    __syncthreads();

    int warp = tid >> 5, lane = tid & 31;
    int d4 = lane << 2;

#define PL(cc, kk) (*(const float4*)&Ps[((cc) * 3 + (kk)) * 128 + d4])

    for (int ii = 0; ii < 8; ii++) {
        int lw = warp * 8 + ii;
        const int4* ip = (const int4*)(wic + (((b << 8) + t0 + lw) << 4));
        int4 q0 = ip[0], q1 = ip[1], q2 = ip[2], q3 = ip[3];
        int c[16] = {q0.x, q0.y, q0.z, q0.w, q1.x, q1.y, q1.z, q1.w,
                     q2.x, q2.y, q2.z, q2.w, q3.x, q3.y, q3.z, q3.w};

        float4 a = PL(c[0], 1);
        float4 r = PL(c[1], 2);
        float4 m;
        m.x = a.x + r.x; m.y = a.y + r.y; m.z = a.z + r.z; m.w = a.w + r.w;
#pragma unroll
        for (int t = 1; t < 15; t++) {
            float4 ce = PL(c[t], 1);
            float4 le = PL(c[t - 1], 0);
            float4 re = PL(c[t + 1], 2);
            float vx = ce.x + le.x + re.x;
            float vy = ce.y + le.y + re.y;
            float vz = ce.z + le.z + re.z;
            float vw = ce.w + le.w + re.w;
            m.x = fmaxf(m.x, vx); m.y = fmaxf(m.y, vy);
            m.z = fmaxf(m.z, vz); m.w = fmaxf(m.w, vw);
        }
        {
            float4 ce = PL(c[15], 1);
            float4 le = PL(c[14], 0);
            m.x = fmaxf(m.x, ce.x + le.x); m.y = fmaxf(m.y, ce.y + le.y);
            m.z = fmaxf(m.z, ce.z + le.z); m.w = fmaxf(m.w, ce.w + le.w);
        }
        Fs[(d4 + 0) * 65 + lw] = m.x;
        Fs[(d4 + 1) * 65 + lw] = m.y;
        Fs[(d4 + 2) * 65 + lw] = m.z;
        Fs[(d4 + 3) * 65 + lw] = m.w;
    }
#undef PL
    __syncthreads();

    int dout = tid >> 1;
    int half = tid & 1;
    const float* fsrc = Fs + dout * 65 + (half << 5);
    float* gdst = out1 + (((b << 7) + dout) << 8) + t0 + (half << 5);
#pragma unroll
    for (int i = 0; i < 8; i++) {
        float4 v = make_float4(fsrc[i * 4 + 0], fsrc[i * 4 + 1],
                               fsrc[i * 4 + 2], fsrc[i * 4 + 3]);
        ((float4*)gdst)[i] = v;
    }
}
#define SMEM_CHAR 229888

// ---------------------------------------------------------------------------
// K3: word path GEMM, 512 threads (16 warps -> 4 warps/SMSP for latency hiding).
// Block = (b, 64-token tile) x 128 dout, K = 3 taps x 128 din.
// Warp owns 4 tokens; lane owns a dout-quad. 16 FFMA + 5 LDS per din iter.
// Weight taps double-buffered via cp.async; emb tile + halo in smem.
// ---------------------------------------------------------------------------
#define CP16(dst_s, src_g) \
    asm volatile("cp.async.cg.shared.global [%0], [%1], 16;\n" :: "r"(dst_s), "l"(src_g))

#define SMEM_WORD (66 * 128 * 4 + 2 * 16384 * 4)   // 33792 + 131072 = 164864 B

__global__ void __launch_bounds__(512, 1)
k_word(const int* __restrict__ wv, const float* __restrict__ wtab,
       const float* __restrict__ wb, float* __restrict__ out0) {
    extern __shared__ float sm[];
    float* Es = sm;                 // 66 * 128 floats (token halo)
    float* Ws = sm + 66 * 128;      // 2 * 16384 floats (double-buffered tap)
    int tid = threadIdx.x;          // 512 threads
    int b  = blockIdx.x >> 2;
    int t0 = (blockIdx.x & 3) << 6;

    unsigned ws_base = (unsigned)__cvta_generic_to_shared(Ws);
    {   // prefetch tap 0 weights into buffer 0 (4096 float4 / 512 thr = 8 each)
        const float* g0 = g_Wt_word;
#pragma unroll
        for (int i = 0; i < 8; i++) {
            int o4 = tid + i * 512;
            CP16(ws_base + o4 * 16, g0 + o4 * 4);
        }
        asm volatile("cp.async.commit_group;\n");
    }
    // embedding gather: rows v=0..65 <-> global token t0+v-1 (zero padded)
    for (int item = tid; item < 66 * 32; item += 512) {
        int v = item >> 5, q = item & 31;
        int gt = t0 + v - 1;
        float4 val = make_float4(0.f, 0.f, 0.f, 0.f);
        if ((unsigned)gt < 256u) {
            int idx = __ldg(wv + (b << 8) + gt);
            val = __ldg((const float4*)wtab + idx * 32 + q);
        }
        ((float4*)Es)[(v << 5) + q] = val;
    }
    asm volatile("cp.async.wait_group 0;\n");
    __syncthreads();

    int warp = tid >> 5, col = tid & 31;
    int tb = warp << 2;             // 4 tokens per warp (16 warps * 4 = 64)
    float acc[4][4];
#pragma unroll
    for (int i = 0; i < 4; i++)
        acc[i][0] = acc[i][1] = acc[i][2] = acc[i][3] = 0.f;

#pragma unroll
    for (int tap = 0; tap < 3; tap++) {
        if (tap < 2) {  // prefetch next tap into the other buffer
            const float* gn = g_Wt_word + (tap + 1) * 16384;
            unsigned dstb = ws_base + (((tap + 1) & 1) * 16384) * 4;
#pragma unroll
            for (int i = 0; i < 8; i++) {
                int o4 = tid + i * 512;
                CP16(dstb + o4 * 16, gn + o4 * 4);
            }
            asm volatile("cp.async.commit_group;\n");
        }
        const float* W  = Ws + (tap & 1) * 16384;
        const float* Er = Es + (tb + tap) * 128;
#pragma unroll 4
        for (int din = 0; din < 128; din++) {
            float4 w = ((const float4*)(W + din * 128))[col];
            float e0 = Er[din];
            float e1 = Er[128 + din];
            float e2 = Er[256 + din];
            float e3 = Er[384 + din];
            acc[0][0] = fmaf(e0, w.x, acc[0][0]);
            acc[0][1] = fmaf(e0, w.y, acc[0][1]);
            acc[0][2] = fmaf(e0, w.z, acc[0][2]);
            acc[0][3] = fmaf(e0, w.w, acc[0][3]);
            acc[1][0] = fmaf(e1, w.x, acc[1][0]);
            acc[1][1] = fmaf(e1, w.y, acc[1][1]);
            acc[1][2] = fmaf(e1, w.z, acc[1][2]);
            acc[1][3] = fmaf(e1, w.w, acc[1][3]);
            acc[2][0] = fmaf(e2, w.x, acc[2][0]);
            acc[2][1] = fmaf(e2, w.y, acc[2][1]);
            acc[2][2] = fmaf(e2, w.z, acc[2][2]);
            acc[2][3] = fmaf(e2, w.w, acc[2][3]);
            acc[3][0] = fmaf(e3, w.x, acc[3][0]);
            acc[3][1] = fmaf(e3, w.y, acc[3][1]);
            acc[3][2] = fmaf(e3, w.z, acc[3][2]);
            acc[3][3] = fmaf(e3, w.w, acc[3][3]);
        }
        if (tap < 2) {
            asm volatile("cp.async.wait_group 0;\n");
            __syncthreads();
        }
    }

    // epilogue: bias + float4 store of 4 consecutive tokens per dout
#pragma unroll
    for (int j = 0; j < 4; j++) {
        int dout = (col << 2) + j;
        float bias = __ldg(wb + dout);
        float4 v = make_float4(acc[0][j] + bias, acc[1][j] + bias,
                               acc[2][j] + bias, acc[3][j] + bias);
        *(float4*)(out0 + (((b << 7) + dout) << 8) + t0 + tb) = v;
    }
}

// ---------------------------------------------------------------------------
extern "C" void kernel_launch(void* const* d_in, const int* in_sizes, int n_in,
                              void* d_out, int out_size) {
    const int*   wv   = (const int*)d_in[0];    // word_vector  [32,256]
    const int*   wic  = (const int*)d_in[1];    // words_in_char [32,256,16]
    const float* wtab = (const float*)d_in[2];  // word_table [50000,128]
    const float* ctab = (const float*)d_in[3];  // chr_table [128,128]
    const float* wcw  = (const float*)d_in[4];  // conv_chr_w [128,128,3]
    const float* wcb  = (const float*)d_in[5];  // conv_chr_b [128]
    const float* www  = (const float*)d_in[6];  // conv_word_w [128,128,3]
    const float* wwb  = (const float*)d_in[7];  // conv_word_b [128]
    float* out  = (float*)d_out;
    float* out0 = out;                    // [32,128,256] word conv
    float* out1 = out + 32 * 128 * 256;   // [32,128,256] char feats

    cudaFuncSetAttribute(k_setup, cudaFuncAttributeMaxDynamicSharedMemorySize, SMEM_SETUP);
    cudaFuncSetAttribute(k_char,  cudaFuncAttributeMaxDynamicSharedMemorySize, SMEM_CHAR);
    cudaFuncSetAttribute(k_word,  cudaFuncAttributeMaxDynamicSharedMemorySize, SMEM_WORD);

    k_setup<<<256, 256, SMEM_SETUP>>>(www, wcw, ctab, wcb);
    k_char<<<128, 256, SMEM_CHAR>>>(wic, out1);
    k_word<<<128, 512, SMEM_WORD>>>(wv, wtab, wwb, out0);
}

// round 11
// speedup vs baseline: 1.1593x; 1.0820x over previous
#include <cuda_runtime.h>
#include <cstdint>

// Problem constants: B=32, L=256, C=16, D=128, char vocab = 128.
// out: float32 [2, 32, 128, 256]; out[0]=word conv, out[1]=char feats (transposed).

__device__ float g_Wt_word[3 * 128 * 128];  // [k][din][dout]
__device__ float g_P      [128 * 3 * 128];  // [c][k][dout], bias folded into k=1

// ---------------------------------------------------------------------------
// K1 "setup": blocks 0-191 transpose word weights [dout][din][k]->[k][din][dout];
// blocks 192-255 compute P[c][k][dout] (2 c's per block) straight from the
// ORIGINAL chr-weight layout via a 387-pitch smem stage.
// Staging now uses affine indexing + float4 loads -> full MLP (was the 27us bug).
// ---------------------------------------------------------------------------
#define WPITCH 387   // 387 % 32 = 3, gcd(3,32)=1 -> conflict-free strided reads

__global__ void k_setup(const float* __restrict__ ww, const float* __restrict__ wc,
                        const float* __restrict__ ctab, const float* __restrict__ wcb) {
    int tid = threadIdx.x;  // 256
    if (blockIdx.x < 192) {
        int o = blockIdx.x * 256 + tid;                  // 192*256 = 49152
        int k = o >> 14, r = o & 16383, din = r >> 7, dout = r & 127;
        g_Wt_word[o] = ww[dout * 384 + din * 3 + k];
        return;
    }
    extern __shared__ float s[];
    float* Wst  = s;                   // 128 * 387 floats
    float* erow = s + 128 * WPITCH;    // 2 * 128 floats
    int blk = blockIdx.x - 192;        // 0..63

    // stage chr weights: Wst[d*387 + r] = wc[d*384 + r].
    // float4 loads (wc contiguous); a float4 never straddles a 384-float row.
    {
        const float4* src = (const float4*)wc;   // 12288 float4
#pragma unroll 4
        for (int i4 = tid; i4 < 12288; i4 += 256) {
            float4 v = __ldg(src + i4);
            int o = i4 << 2;                 // element offset
            int d = (o * 21846) >> 23;       // o/384 for o < 49152 (exact)
            int r = o - d * 384;
            float* w = Wst + d * WPITCH + r;
            w[0] = v.x; w[1] = v.y; w[2] = v.z; w[3] = v.w;
        }
    }
    int c0 = blk * 2;
    int sub = tid >> 7, d = tid & 127;
    erow[sub * 128 + d] = ctab[(c0 + sub) * 128 + d];
    __syncthreads();

    const float* er = erow + sub * 128;
    const float* wr = Wst + d * WPITCH;
    float a0 = 0.f, a1 = 0.f, a2 = 0.f;
#pragma unroll 8
    for (int din = 0; din < 128; din++) {
        float e = er[din];
        a0 = fmaf(e, wr[din * 3 + 0], a0);
        a1 = fmaf(e, wr[din * 3 + 1], a1);
        a2 = fmaf(e, wr[din * 3 + 2], a2);
    }
    int c = c0 + sub;
    g_P[(c * 3 + 0) * 128 + d] = a0;
    g_P[(c * 3 + 1) * 128 + d] = a1 + wcb[d];   // bias folded into center tap
    g_P[(c * 3 + 2) * 128 + d] = a2;
}
#define SMEM_SETUP ((128 * WPITCH + 256) * 4)   // 199168 B

// ---------------------------------------------------------------------------
// K2: char path. Block = (b, 64-token chunk). P in smem (192 KB).
// Warp handles 8 words; lane owns a dout-quad -> conflict-free LDS.128.
// ---------------------------------------------------------------------------
__global__ void k_char(const int* __restrict__ wic, float* __restrict__ out1) {
    extern __shared__ float sm[];
    float* Ps = sm;              // 49152 floats
    float* Fs = sm + 49152;      // 128 * 65 floats
    int tid = threadIdx.x;       // 256 threads
    int b  = blockIdx.x >> 2;
    int t0 = (blockIdx.x & 3) << 6;

    {   // load P into smem (L2-resident: 192 KB)
        const float4* src = (const float4*)g_P;
        float4* dst = (float4*)Ps;
#pragma unroll
        for (int i = 0; i < 48; i++) dst[tid + i * 256] = src[tid + i * 256];
    }
    __syncthreads();

    int warp = tid >> 5, lane = tid & 31;
    int d4 = lane << 2;

#define PL(cc, kk) (*(const float4*)&Ps[((cc) * 3 + (kk)) * 128 + d4])

    for (int ii = 0; ii < 8; ii++) {
        int lw = warp * 8 + ii;
        const int4* ip = (const int4*)(wic + (((b << 8) + t0 + lw) << 4));
        int4 q0 = ip[0], q1 = ip[1], q2 = ip[2], q3 = ip[3];
        int c[16] = {q0.x, q0.y, q0.z, q0.w, q1.x, q1.y, q1.z, q1.w,
                     q2.x, q2.y, q2.z, q2.w, q3.x, q3.y, q3.z, q3.w};

        float4 a = PL(c[0], 1);
        float4 r = PL(c[1], 2);
        float4 m;
        m.x = a.x + r.x; m.y = a.y + r.y; m.z = a.z + r.z; m.w = a.w + r.w;
#pragma unroll
        for (int t = 1; t < 15; t++) {
            float4 ce = PL(c[t], 1);
            float4 le = PL(c[t - 1], 0);
            float4 re = PL(c[t + 1], 2);
            float vx = ce.x + le.x + re.x;
            float vy = ce.y + le.y + re.y;
            float vz = ce.z + le.z + re.z;
            float vw = ce.w + le.w + re.w;
            m.x = fmaxf(m.x, vx); m.y = fmaxf(m.y, vy);
            m.z = fmaxf(m.z, vz); m.w = fmaxf(m.w, vw);
        }
        {
            float4 ce = PL(c[15], 1);
            float4 le = PL(c[14], 0);
            m.x = fmaxf(m.x, ce.x + le.x); m.y = fmaxf(m.y, ce.y + le.y);
            m.z = fmaxf(m.z, ce.z + le.z); m.w = fmaxf(m.w, ce.w + le.w);
        }
        Fs[(d4 + 0) * 65 + lw] = m.x;
        Fs[(d4 + 1) * 65 + lw] = m.y;
        Fs[(d4 + 2) * 65 + lw] = m.z;
        Fs[(d4 + 3) * 65 + lw] = m.w;
    }
#undef PL
    __syncthreads();

    int dout = tid >> 1;
    int half = tid & 1;
    const float* fsrc = Fs + dout * 65 + (half << 5);
    float* gdst = out1 + (((b << 7) + dout) << 8) + t0 + (half << 5);
#pragma unroll
    for (int i = 0; i < 8; i++) {
        float4 v = make_float4(fsrc[i * 4 + 0], fsrc[i * 4 + 1],
                               fsrc[i * 4 + 2], fsrc[i * 4 + 3]);
        ((float4*)gdst)[i] = v;
    }
}
#define SMEM_CHAR 229888

// ---------------------------------------------------------------------------
// K3: word path GEMM, 512 threads (16 warps -> 4 warps/SMSP for latency hiding).
// Block = (b, 64-token tile) x 128 dout, K = 3 taps x 128 din.
// Warp owns 4 tokens; lane owns a dout-quad. 16 FFMA + 5 LDS per din iter.
// Weight taps double-buffered via cp.async; emb tile + halo in smem.
// ---------------------------------------------------------------------------
#define CP16(dst_s, src_g) \
    asm volatile("cp.async.cg.shared.global [%0], [%1], 16;\n" :: "r"(dst_s), "l"(src_g))

#define SMEM_WORD (66 * 128 * 4 + 2 * 16384 * 4)   // 33792 + 131072 = 164864 B

__global__ void __launch_bounds__(512, 1)
k_word(const int* __restrict__ wv, const float* __restrict__ wtab,
       const float* __restrict__ wb, float* __restrict__ out0) {
    extern __shared__ float sm[];
    float* Es = sm;                 // 66 * 128 floats (token halo)
    float* Ws = sm + 66 * 128;      // 2 * 16384 floats (double-buffered tap)
    int tid = threadIdx.x;          // 512 threads
    int b  = blockIdx.x >> 2;
    int t0 = (blockIdx.x & 3) << 6;

    unsigned ws_base = (unsigned)__cvta_generic_to_shared(Ws);
    {   // prefetch tap 0 weights into buffer 0 (4096 float4 / 512 thr = 8 each)
        const float* g0 = g_Wt_word;
#pragma unroll
        for (int i = 0; i < 8; i++) {
            int o4 = tid + i * 512;
            CP16(ws_base + o4 * 16, g0 + o4 * 4);
        }
        asm volatile("cp.async.commit_group;\n");
    }
    // embedding gather: rows v=0..65 <-> global token t0+v-1 (zero padded)
    for (int item = tid; item < 66 * 32; item += 512) {
        int v = item >> 5, q = item & 31;
        int gt = t0 + v - 1;
        float4 val = make_float4(0.f, 0.f, 0.f, 0.f);
        if ((unsigned)gt < 256u) {
            int idx = __ldg(wv + (b << 8) + gt);
            val = __ldg((const float4*)wtab + idx * 32 + q);
        }
        ((float4*)Es)[(v << 5) + q] = val;
    }
    asm volatile("cp.async.wait_group 0;\n");
    __syncthreads();

    int warp = tid >> 5, col = tid & 31;
    int tb = warp << 2;             // 4 tokens per warp (16 warps * 4 = 64)
    float acc[4][4];
#pragma unroll
    for (int i = 0; i < 4; i++)
        acc[i][0] = acc[i][1] = acc[i][2] = acc[i][3] = 0.f;

#pragma unroll
    for (int tap = 0; tap < 3; tap++) {
        if (tap < 2) {  // prefetch next tap into the other buffer
            const float* gn = g_Wt_word + (tap + 1) * 16384;
            unsigned dstb = ws_base + (((tap + 1) & 1) * 16384) * 4;
#pragma unroll
            for (int i = 0; i < 8; i++) {
                int o4 = tid + i * 512;
                CP16(dstb + o4 * 16, gn + o4 * 4);
            }
            asm volatile("cp.async.commit_group;\n");
        }
        const float* W  = Ws + (tap & 1) * 16384;
        const float* Er = Es + (tb + tap) * 128;
#pragma unroll 4
        for (int din = 0; din < 128; din++) {
            float4 w = ((const float4*)(W + din * 128))[col];
            float e0 = Er[din];
            float e1 = Er[128 + din];
            float e2 = Er[256 + din];
            float e3 = Er[384 + din];
            acc[0][0] = fmaf(e0, w.x, acc[0][0]);
            acc[0][1] = fmaf(e0, w.y, acc[0][1]);
            acc[0][2] = fmaf(e0, w.z, acc[0][2]);
            acc[0][3] = fmaf(e0, w.w, acc[0][3]);
            acc[1][0] = fmaf(e1, w.x, acc[1][0]);
            acc[1][1] = fmaf(e1, w.y, acc[1][1]);
            acc[1][2] = fmaf(e1, w.z, acc[1][2]);
            acc[1][3] = fmaf(e1, w.w, acc[1][3]);
            acc[2][0] = fmaf(e2, w.x, acc[2][0]);
            acc[2][1] = fmaf(e2, w.y, acc[2][1]);
            acc[2][2] = fmaf(e2, w.z, acc[2][2]);
            acc[2][3] = fmaf(e2, w.w, acc[2][3]);
            acc[3][0] = fmaf(e3, w.x, acc[3][0]);
            acc[3][1] = fmaf(e3, w.y, acc[3][1]);
            acc[3][2] = fmaf(e3, w.z, acc[3][2]);
            acc[3][3] = fmaf(e3, w.w, acc[3][3]);
        }
        if (tap < 2) {
            asm volatile("cp.async.wait_group 0;\n");
            __syncthreads();
        }
    }

    // epilogue: bias + float4 store of 4 consecutive tokens per dout
#pragma unroll
    for (int j = 0; j < 4; j++) {
        int dout = (col << 2) + j;
        float bias = __ldg(wb + dout);
        float4 v = make_float4(acc[0][j] + bias, acc[1][j] + bias,
                               acc[2][j] + bias, acc[3][j] + bias);
        *(float4*)(out0 + (((b << 7) + dout) << 8) + t0 + tb) = v;
    }
}

// ---------------------------------------------------------------------------
extern "C" void kernel_launch(void* const* d_in, const int* in_sizes, int n_in,
                              void* d_out, int out_size) {
    const int*   wv   = (const int*)d_in[0];    // word_vector  [32,256]
    const int*   wic  = (const int*)d_in[1];    // words_in_char [32,256,16]
    const float* wtab = (const float*)d_in[2];  // word_table [50000,128]
    const float* ctab = (const float*)d_in[3];  // chr_table [128,128]
    const float* wcw  = (const float*)d_in[4];  // conv_chr_w [128,128,3]
    const float* wcb  = (const float*)d_in[5];  // conv_chr_b [128]
    const float* www  = (const float*)d_in[6];  // conv_word_w [128,128,3]
    const float* wwb  = (const float*)d_in[7];  // conv_word_b [128]
    float* out  = (float*)d_out;
    float* out0 = out;                    // [32,128,256] word conv
    float* out1 = out + 32 * 128 * 256;   // [32,128,256] char feats

    cudaFuncSetAttribute(k_setup, cudaFuncAttributeMaxDynamicSharedMemorySize, SMEM_SETUP);
    cudaFuncSetAttribute(k_char,  cudaFuncAttributeMaxDynamicSharedMemorySize, SMEM_CHAR);
    cudaFuncSetAttribute(k_word,  cudaFuncAttributeMaxDynamicSharedMemorySize, SMEM_WORD);

    k_setup<<<256, 256, SMEM_SETUP>>>(www, wcw, ctab, wcb);
    k_char<<<128, 256, SMEM_CHAR>>>(wic, out1);
    k_word<<<128, 512, SMEM_WORD>>>(wv, wtab, wwb, out0);
}